// round 15
// baseline (speedup 1.0000x reference)
#include <cuda_runtime.h>
#include <math.h>

// Scattering third-order via Parseval identity:
//   out[b,i,j] = (1/MN^2) * sum_k F_j[k]^2 * Re( conj(X[b,k]) * XA_i[b,k] )
// X = fft2(x), XA_i = fft2(abs_eps(ifft2(F_i * X))).
//
// FFT engine: 4 threads per 128-pt line, 32 complex elements in registers.
// Inverse uses DIF (natural -> bitrev), forward uses DIT (bitrev -> natural):
// the spatial domain stays bit-reversed and abs is pointwise, so no
// permutations appear in the main kernel.

#define MDIM   128
#define MN     16384
#define NFI    32
#define NPAIR  672
#define BATCH  2
#define EPSV   1e-6f

__device__ float2 g_X[BATCH][MN];          // fft2(x), natural order
__device__ float2 g_T[BATCH][MN];          // row-FFT intermediate (bitrev pos)
__device__ float  g_H[BATCH][NFI][MN];     // Re(conj(X) * XA_i)

// ---------------------------------------------------------------------------
__device__ __forceinline__ float2 shflx(float2 a, int m) {
    a.x = __shfl_xor_sync(0xffffffffu, a.x, m);
    a.y = __shfl_xor_sync(0xffffffffu, a.y, m);
    return a;
}

// Conflict-free smem layout (float2 index) for logical (row, col).
__device__ __forceinline__ int smaddr(int row, int col) {
    int pc = ((col & 31) << 2) | (col >> 5);
    int s  = ((row >> 5) & 3) | ((row & 3) << 2);
    return (row << 7) + (pc ^ s);
}

template<int SGN>  // SGN = -1 forward (numpy fft), +1 inverse (unnormalized)
__device__ __forceinline__ float2 cmulw(float2 a, float2 w) {
    float wi = (float)SGN * w.y;
    return make_float2(a.x * w.x - a.y * wi, a.x * wi + a.y * w.x);
}

template<int SGN>
__device__ __forceinline__ void bfly_dif(float2& a, float2& b, float2 w) {
    float ur = a.x - b.x, ui = a.y - b.y;
    a.x += b.x; a.y += b.y;
    float wi = (float)SGN * w.y;
    b.x = ur * w.x - ui * wi;
    b.y = ur * wi + ui * w.x;
}

template<int SGN>
__device__ __forceinline__ void bfly_dit(float2& a, float2& b, float2 w) {
    float wi = (float)SGN * w.y;
    float tr = b.x * w.x - b.y * wi;
    float ti = b.x * wi + b.y * w.x;
    b.x = a.x - tr; b.y = a.y - ti;
    a.x += tr; a.y += ti;
}

// DIF: natural input -> bit-reversed output. Thread t owns positions 32t+j.
template<int SGN>
__device__ __forceinline__ void dif_line(float2 v[32], int t, const float2* __restrict__ tw) {
    {   // len=128 (span 64, cross t^2), m = 32*(t&1)+j
        const float2* twm = tw + ((t & 1) << 5);
        const bool hi = (t >= 2);
        #pragma unroll
        for (int j = 0; j < 32; ++j) {
            float2 a = v[j];
            float2 p = shflx(a, 2);
            if (!hi) { v[j] = make_float2(a.x + p.x, a.y + p.y); }
            else     { v[j] = cmulw<SGN>(make_float2(p.x - a.x, p.y - a.y), twm[j]); }
        }
    }
    {   // len=64 (span 32, cross t^1), m = 2j
        const bool hi = (t & 1);
        #pragma unroll
        for (int j = 0; j < 32; ++j) {
            float2 a = v[j];
            float2 p = shflx(a, 1);
            if (!hi) { v[j] = make_float2(a.x + p.x, a.y + p.y); }
            else     { v[j] = cmulw<SGN>(make_float2(p.x - a.x, p.y - a.y), tw[2 * j]); }
        }
    }
    #pragma unroll
    for (int j = 0; j < 16; ++j) bfly_dif<SGN>(v[j], v[j + 16], tw[4 * j]);
    #pragma unroll
    for (int b = 0; b < 32; b += 16)
        #pragma unroll
        for (int j = 0; j < 8; ++j) bfly_dif<SGN>(v[b + j], v[b + j + 8], tw[8 * j]);
    #pragma unroll
    for (int b = 0; b < 32; b += 8)
        #pragma unroll
        for (int j = 0; j < 4; ++j) bfly_dif<SGN>(v[b + j], v[b + j + 4], tw[16 * j]);
    #pragma unroll
    for (int b = 0; b < 32; b += 4)
        #pragma unroll
        for (int j = 0; j < 2; ++j) bfly_dif<SGN>(v[b + j], v[b + j + 2], tw[32 * j]);
    #pragma unroll
    for (int b = 0; b < 32; b += 2) {
        float2 u = v[b], w2 = v[b + 1];
        v[b]     = make_float2(u.x + w2.x, u.y + w2.y);
        v[b + 1] = make_float2(u.x - w2.x, u.y - w2.y);
    }
}

// DIT: bit-reversed input -> natural output.
template<int SGN>
__device__ __forceinline__ void dit_line(float2 v[32], int t, const float2* __restrict__ tw) {
    #pragma unroll
    for (int b = 0; b < 32; b += 2) {
        float2 u = v[b], w2 = v[b + 1];
        v[b]     = make_float2(u.x + w2.x, u.y + w2.y);
        v[b + 1] = make_float2(u.x - w2.x, u.y - w2.y);
    }
    #pragma unroll
    for (int b = 0; b < 32; b += 4)
        #pragma unroll
        for (int j = 0; j < 2; ++j) bfly_dit<SGN>(v[b + j], v[b + j + 2], tw[32 * j]);
    #pragma unroll
    for (int b = 0; b < 32; b += 8)
        #pragma unroll
        for (int j = 0; j < 4; ++j) bfly_dit<SGN>(v[b + j], v[b + j + 4], tw[16 * j]);
    #pragma unroll
    for (int b = 0; b < 32; b += 16)
        #pragma unroll
        for (int j = 0; j < 8; ++j) bfly_dit<SGN>(v[b + j], v[b + j + 8], tw[8 * j]);
    #pragma unroll
    for (int j = 0; j < 16; ++j) bfly_dit<SGN>(v[j], v[j + 16], tw[4 * j]);
    {   // len=64 (cross t^1)
        const bool hi = (t & 1);
        #pragma unroll
        for (int j = 0; j < 32; ++j) {
            float2 a = v[j];
            if (hi) a = cmulw<SGN>(a, tw[2 * j]);
            float2 p = shflx(a, 1);
            v[j] = hi ? make_float2(p.x - a.x, p.y - a.y)
                      : make_float2(a.x + p.x, a.y + p.y);
        }
    }
    {   // len=128 (cross t^2)
        const float2* twm = tw + ((t & 1) << 5);
        const bool hi = (t >= 2);
        #pragma unroll
        for (int j = 0; j < 32; ++j) {
            float2 a = v[j];
            if (hi) a = cmulw<SGN>(a, twm[j]);
            float2 p = shflx(a, 2);
            v[j] = hi ? make_float2(p.x - a.x, p.y - a.y)
                      : make_float2(a.x + p.x, a.y + p.y);
        }
    }
}

__device__ __forceinline__ void build_tw(float2* tw, int tid) {
    if (tid < 64) {
        float s, c;
        sincospif((float)tid / 64.f, &s, &c);   // e^{+2*pi*i*tid/128}
        tw[tid] = make_float2(c, s);
    }
}

// ---------------------------------------------------------------------------
// Kernel 1a: row FFTs of x.  grid (BATCH, 4), block 128 (32 lines x 4 thr).
// g_T[b][line][pos] = RowFFT(line) at bit-reversed position pos.
// ---------------------------------------------------------------------------
__global__ __launch_bounds__(128) void k_fft_rows(const float* __restrict__ x,
                                                  float* __restrict__ dummy) {
    __shared__ float2 tw[64];
    const int tid = threadIdx.x;
    build_tw(tw, tid);
    __syncthreads();

    const int b    = blockIdx.x;
    const int line = blockIdx.y * 32 + (tid >> 2);
    const int t    = tid & 3;

    float2 v[32];
    const float* xb = x + b * MN + line * MDIM + 32 * t;
    #pragma unroll
    for (int j = 0; j < 32; ++j) v[j] = make_float2(xb[j], 0.f);

    dif_line<-1>(v, t, tw);

    float2* dst = &g_T[b][line * MDIM + 32 * t];
    #pragma unroll
    for (int j = 0; j < 32; ++j) dst[j] = v[j];
}

// ---------------------------------------------------------------------------
// Kernel 1b: column FFTs.  grid (BATCH, 4), block 128 (32 pos-cols x 4 thr).
// Writes g_X in NATURAL order via bitrev on both indices.
// ---------------------------------------------------------------------------
__global__ __launch_bounds__(128) void k_fft_cols() {
    __shared__ float2 tw[64];
    const int tid = threadIdx.x;
    build_tw(tw, tid);
    __syncthreads();

    const int b = blockIdx.x;
    const int q = blockIdx.y * 32 + (tid >> 2);   // pos-column
    const int t = tid & 3;

    float2 v[32];
    #pragma unroll
    for (int j = 0; j < 32; ++j) v[j] = g_T[b][(32 * t + j) * MDIM + q];

    dif_line<-1>(v, t, tw);

    const int bq = (int)(__brev((unsigned)q) >> 25);
    #pragma unroll
    for (int j = 0; j < 32; ++j) {
        int br = (int)(__brev((unsigned)(32 * t + j)) >> 25);
        g_X[b][br * MDIM + bq] = v[j];
    }
}

// ---------------------------------------------------------------------------
// Kernel zero: clear output (accumulated via atomics by k_reduce).
// ---------------------------------------------------------------------------
__global__ void k_zero(float* __restrict__ out, int n) {
    int i = blockIdx.x * blockDim.x + threadIdx.x;
    if (i < n) out[i] = 0.f;
}

// ---------------------------------------------------------------------------
// Kernel 2: per (b,i): H = Re(conj(X) * fft2(abs_eps(ifft2(F_i*X)))).
// grid = BATCH*NFI, block = 512.
// ---------------------------------------------------------------------------
__global__ __launch_bounds__(512, 1) void k_main(const float* __restrict__ F) {
    extern __shared__ float2 sm[];
    float2* tile = sm;
    float2* tw   = sm + MDIM * MDIM;
    const int tid  = threadIdx.x;
    const int line = tid >> 2, t = tid & 3;
    const int b = blockIdx.x >> 5;
    const int i = blockIdx.x & 31;

    build_tw(tw, tid);
    __syncthreads();

    const int base = line * MDIM + 32 * t;
    const float* __restrict__ Fi = F + i * MN + base;
    float2 v[32];
    #pragma unroll
    for (int j = 0; j < 32; ++j) {
        float  f  = Fi[j];
        float2 xv = g_X[b][base + j];
        v[j] = make_float2(f * xv.x, f * xv.y);
    }

    dif_line<1>(v, t, tw);                           // inverse over cols
    #pragma unroll
    for (int j = 0; j < 32; ++j) tile[smaddr(line, 32 * t + j)] = v[j];
    __syncthreads();
    #pragma unroll
    for (int j = 0; j < 32; ++j) v[j] = tile[smaddr(32 * t + j, line)];
    dif_line<1>(v, t, tw);                           // inverse over rows

    const float sc = 1.f / (float)MN;
    #pragma unroll
    for (int j = 0; j < 32; ++j) {
        float re = v[j].x * sc, im = v[j].y * sc;
        v[j] = make_float2(sqrtf(re * re + im * im + EPSV), 0.f);
    }

    dit_line<-1>(v, t, tw);                          // forward over rows (regs)
    __syncthreads();
    #pragma unroll
    for (int j = 0; j < 32; ++j) tile[smaddr(32 * t + j, line)] = v[j];
    __syncthreads();
    #pragma unroll
    for (int j = 0; j < 32; ++j) v[j] = tile[smaddr(line, 32 * t + j)];
    dit_line<-1>(v, t, tw);                          // forward over cols -> XA natural

    float* __restrict__ Hrow = g_H[b][i] + base;
    #pragma unroll
    for (int j = 0; j < 32; ++j) {
        float2 xv = g_X[b][base + j];
        Hrow[j] = v[j].x * xv.x + v[j].y * xv.y;     // Re(conj(X)*XA)
    }
}

// ---------------------------------------------------------------------------
// Kernel 3: block (i0, b, half) keeps its H half in registers and loops over
// the j-partners of i0, streaming F only.  atomicAdd combines the 2 k-halves.
// grid = (NFI, BATCH, 2), block = 256.
// ---------------------------------------------------------------------------
__global__ __launch_bounds__(256) void k_reduce(const float* __restrict__ F,
                                               float* __restrict__ out) {
    const int i0   = blockIdx.x;
    const int b    = blockIdx.y;
    const int half = blockIdx.z;
    const int tid  = threadIdx.x;

    const int j1 = i0 >> 3, l1 = i0 & 7;
    const int nj = (4 - j1) * 8 + 1;
    // prefix: full groups before j1, plus l1 groups inside
    static const int Gpre[4] = {0, 264, 464, 600};
    const int pbase = Gpre[j1] + l1 * nj;

    // load this block's H half (8192 floats = 2048 float4) into registers
    const float4* __restrict__ H4 =
        (const float4*)(g_H[b][i0]) + half * 2048;
    float4 h[8];
    #pragma unroll
    for (int u = 0; u < 8; ++u) h[u] = H4[u * 256 + tid];

    __shared__ float wsum[8];
    const float scale = 1.f / ((float)MN * (float)MN);

    #pragma unroll 1
    for (int jj = 0; jj < nj; ++jj) {
        const int i1 = (jj < (4 - j1) * 8) ? (j1 + (jj >> 3)) * 8 + (jj & 7) : 32;
        const float4* __restrict__ F4 =
            (const float4*)(F + i1 * MN) + half * 2048;

        float s = 0.f;
        #pragma unroll
        for (int u = 0; u < 8; ++u) {
            float4 fv = F4[u * 256 + tid];
            s += h[u].x * (fv.x * fv.x) + h[u].y * (fv.y * fv.y)
               + h[u].z * (fv.z * fv.z) + h[u].w * (fv.w * fv.w);
        }

        #pragma unroll
        for (int o = 16; o; o >>= 1) s += __shfl_xor_sync(0xffffffffu, s, o);
        if ((tid & 31) == 0) wsum[tid >> 5] = s;
        __syncthreads();
        if (tid < 32) {
            float vv = (tid < 8) ? wsum[tid] : 0.f;
            #pragma unroll
            for (int o = 4; o; o >>= 1) vv += __shfl_xor_sync(0xffffffffu, vv, o);
            if (tid == 0)
                atomicAdd(&out[b * NPAIR + pbase + jj], vv * scale);
        }
        __syncthreads();
    }
}

// ---------------------------------------------------------------------------
extern "C" void kernel_launch(void* const* d_in, const int* in_sizes, int n_in,
                              void* d_out, int out_size) {
    const float* x = (const float*)d_in[0];   // (B,1,128,128) float32
    const float* F = (const float*)d_in[1];   // (1,33,128,128) float32
    float* out = (float*)d_out;               // (B,672) float32

    const int SMEM = (MDIM * MDIM + 64) * (int)sizeof(float2);
    cudaFuncSetAttribute(k_main, cudaFuncAttributeMaxDynamicSharedMemorySize, SMEM);

    k_zero<<<(BATCH * NPAIR + 255) / 256, 256>>>(out, BATCH * NPAIR);
    k_fft_rows<<<dim3(BATCH, 4), 128>>>(x, out);
    k_fft_cols<<<dim3(BATCH, 4), 128>>>();
    k_main<<<BATCH * NFI, 512, SMEM>>>(F);
    k_reduce<<<dim3(NFI, BATCH, 2), 256>>>(F, out);
}

// round 16
// speedup vs baseline: 1.1839x; 1.1839x over previous
#include <cuda_runtime.h>
#include <math.h>

// Scattering third-order via Parseval identity:
//   out[b,i,j] = (1/MN^2) * sum_k F_j[k]^2 * Re( conj(X[b,k]) * XA_i[b,k] )
// X = fft2(x), XA_i = fft2(abs_eps(ifft2(F_i * X))).
//
// FFT engines: register-resident 128-pt lines, cross-thread stages via
// shfl_xor. Inverse uses DIF (natural -> bitrev), forward uses DIT
// (bitrev -> natural): the spatial domain stays bit-reversed and abs is
// pointwise, so no permutations appear in the main kernel.
//  - 4 threads/line (32 elems/thread): used by the small row/col kernels.
//  - 8 threads/line (16 elems/thread): used by k_main at 1024 threads/CTA.

#define MDIM   128
#define MN     16384
#define NFI    32
#define NPAIR  672
#define BATCH  2
#define EPSV   1e-6f

__device__ float2 g_X[BATCH][MN];          // fft2(x), natural order
__device__ float2 g_T[BATCH][MN];          // row-FFT intermediate (bitrev pos)
__device__ float  g_H[BATCH][NFI][MN];     // Re(conj(X) * XA_i)

// ---------------------------------------------------------------------------
__device__ __forceinline__ float2 shflx(float2 a, int m) {
    a.x = __shfl_xor_sync(0xffffffffu, a.x, m);
    a.y = __shfl_xor_sync(0xffffffffu, a.y, m);
    return a;
}

// smem layout (float2 index) for logical (row, col): ~2-way wide-bank worst case.
__device__ __forceinline__ int smaddr(int row, int col) {
    int pc = ((col & 31) << 2) | (col >> 5);
    int s  = ((row >> 5) & 3) | ((row & 3) << 2);
    return (row << 7) + (pc ^ s);
}

template<int SGN>  // SGN = -1 forward (numpy fft), +1 inverse (unnormalized)
__device__ __forceinline__ float2 cmulw(float2 a, float2 w) {
    float wi = (float)SGN * w.y;
    return make_float2(a.x * w.x - a.y * wi, a.x * wi + a.y * w.x);
}

template<int SGN>
__device__ __forceinline__ void bfly_dif(float2& a, float2& b, float2 w) {
    float ur = a.x - b.x, ui = a.y - b.y;
    a.x += b.x; a.y += b.y;
    float wi = (float)SGN * w.y;
    b.x = ur * w.x - ui * wi;
    b.y = ur * wi + ui * w.x;
}

template<int SGN>
__device__ __forceinline__ void bfly_dit(float2& a, float2& b, float2 w) {
    float wi = (float)SGN * w.y;
    float tr = b.x * w.x - b.y * wi;
    float ti = b.x * wi + b.y * w.x;
    b.x = a.x - tr; b.y = a.y - ti;
    a.x += tr; a.y += ti;
}

// ======================== 4-thread engine (32/thread) ======================
template<int SGN>
__device__ __forceinline__ void dif_line4(float2 v[32], int t, const float2* __restrict__ tw) {
    {   const float2* twm = tw + ((t & 1) << 5);
        const bool hi = (t >= 2);
        #pragma unroll
        for (int j = 0; j < 32; ++j) {
            float2 a = v[j], p = shflx(a, 2);
            v[j] = hi ? cmulw<SGN>(make_float2(p.x - a.x, p.y - a.y), twm[j])
                      : make_float2(a.x + p.x, a.y + p.y);
        }
    }
    {   const bool hi = (t & 1);
        #pragma unroll
        for (int j = 0; j < 32; ++j) {
            float2 a = v[j], p = shflx(a, 1);
            v[j] = hi ? cmulw<SGN>(make_float2(p.x - a.x, p.y - a.y), tw[2 * j])
                      : make_float2(a.x + p.x, a.y + p.y);
        }
    }
    #pragma unroll
    for (int j = 0; j < 16; ++j) bfly_dif<SGN>(v[j], v[j + 16], tw[4 * j]);
    #pragma unroll
    for (int b = 0; b < 32; b += 16)
        #pragma unroll
        for (int j = 0; j < 8; ++j) bfly_dif<SGN>(v[b + j], v[b + j + 8], tw[8 * j]);
    #pragma unroll
    for (int b = 0; b < 32; b += 8)
        #pragma unroll
        for (int j = 0; j < 4; ++j) bfly_dif<SGN>(v[b + j], v[b + j + 4], tw[16 * j]);
    #pragma unroll
    for (int b = 0; b < 32; b += 4)
        #pragma unroll
        for (int j = 0; j < 2; ++j) bfly_dif<SGN>(v[b + j], v[b + j + 2], tw[32 * j]);
    #pragma unroll
    for (int b = 0; b < 32; b += 2) {
        float2 u = v[b], w2 = v[b + 1];
        v[b]     = make_float2(u.x + w2.x, u.y + w2.y);
        v[b + 1] = make_float2(u.x - w2.x, u.y - w2.y);
    }
}

// ======================== 8-thread engine (16/thread) ======================
// Thread t in [0,8) owns positions 16t+j, j in [0,16).
template<int SGN>
__device__ __forceinline__ void dif_line8(float2 v[16], int t, const float2* __restrict__ tw) {
    {   // len=128 (span 64, cross t^4), m = 16(t&3)+j
        const float2* twm = tw + ((t & 3) << 4);
        const bool hi = (t & 4);
        #pragma unroll
        for (int j = 0; j < 16; ++j) {
            float2 a = v[j], p = shflx(a, 4);
            v[j] = hi ? cmulw<SGN>(make_float2(p.x - a.x, p.y - a.y), twm[j])
                      : make_float2(a.x + p.x, a.y + p.y);
        }
    }
    {   // len=64 (span 32, cross t^2), m = 32(t&1)+2j
        const float2* twm = tw + ((t & 1) << 5);
        const bool hi = (t & 2);
        #pragma unroll
        for (int j = 0; j < 16; ++j) {
            float2 a = v[j], p = shflx(a, 2);
            v[j] = hi ? cmulw<SGN>(make_float2(p.x - a.x, p.y - a.y), twm[2 * j])
                      : make_float2(a.x + p.x, a.y + p.y);
        }
    }
    {   // len=32 (span 16, cross t^1), m = 4j
        const bool hi = (t & 1);
        #pragma unroll
        for (int j = 0; j < 16; ++j) {
            float2 a = v[j], p = shflx(a, 1);
            v[j] = hi ? cmulw<SGN>(make_float2(p.x - a.x, p.y - a.y), tw[4 * j])
                      : make_float2(a.x + p.x, a.y + p.y);
        }
    }
    #pragma unroll
    for (int j = 0; j < 8; ++j) bfly_dif<SGN>(v[j], v[j + 8], tw[8 * j]);
    #pragma unroll
    for (int b = 0; b < 16; b += 8)
        #pragma unroll
        for (int j = 0; j < 4; ++j) bfly_dif<SGN>(v[b + j], v[b + j + 4], tw[16 * j]);
    #pragma unroll
    for (int b = 0; b < 16; b += 4)
        #pragma unroll
        for (int j = 0; j < 2; ++j) bfly_dif<SGN>(v[b + j], v[b + j + 2], tw[32 * j]);
    #pragma unroll
    for (int b = 0; b < 16; b += 2) {
        float2 u = v[b], w2 = v[b + 1];
        v[b]     = make_float2(u.x + w2.x, u.y + w2.y);
        v[b + 1] = make_float2(u.x - w2.x, u.y - w2.y);
    }
}

template<int SGN>
__device__ __forceinline__ void dit_line8(float2 v[16], int t, const float2* __restrict__ tw) {
    #pragma unroll
    for (int b = 0; b < 16; b += 2) {
        float2 u = v[b], w2 = v[b + 1];
        v[b]     = make_float2(u.x + w2.x, u.y + w2.y);
        v[b + 1] = make_float2(u.x - w2.x, u.y - w2.y);
    }
    #pragma unroll
    for (int b = 0; b < 16; b += 4)
        #pragma unroll
        for (int j = 0; j < 2; ++j) bfly_dit<SGN>(v[b + j], v[b + j + 2], tw[32 * j]);
    #pragma unroll
    for (int b = 0; b < 16; b += 8)
        #pragma unroll
        for (int j = 0; j < 4; ++j) bfly_dit<SGN>(v[b + j], v[b + j + 4], tw[16 * j]);
    #pragma unroll
    for (int j = 0; j < 8; ++j) bfly_dit<SGN>(v[j], v[j + 8], tw[8 * j]);
    {   // len=32 (cross t^1), m = 4j
        const bool hi = (t & 1);
        #pragma unroll
        for (int j = 0; j < 16; ++j) {
            float2 a = v[j];
            if (hi) a = cmulw<SGN>(a, tw[4 * j]);
            float2 p = shflx(a, 1);
            v[j] = hi ? make_float2(p.x - a.x, p.y - a.y)
                      : make_float2(a.x + p.x, a.y + p.y);
        }
    }
    {   // len=64 (cross t^2), m = 32(t&1)+2j
        const float2* twm = tw + ((t & 1) << 5);
        const bool hi = (t & 2);
        #pragma unroll
        for (int j = 0; j < 16; ++j) {
            float2 a = v[j];
            if (hi) a = cmulw<SGN>(a, twm[2 * j]);
            float2 p = shflx(a, 2);
            v[j] = hi ? make_float2(p.x - a.x, p.y - a.y)
                      : make_float2(a.x + p.x, a.y + p.y);
        }
    }
    {   // len=128 (cross t^4), m = 16(t&3)+j
        const float2* twm = tw + ((t & 3) << 4);
        const bool hi = (t & 4);
        #pragma unroll
        for (int j = 0; j < 16; ++j) {
            float2 a = v[j];
            if (hi) a = cmulw<SGN>(a, twm[j]);
            float2 p = shflx(a, 4);
            v[j] = hi ? make_float2(p.x - a.x, p.y - a.y)
                      : make_float2(a.x + p.x, a.y + p.y);
        }
    }
}

__device__ __forceinline__ void build_tw(float2* tw, int tid) {
    if (tid < 64) {
        float s, c;
        sincospif((float)tid / 64.f, &s, &c);   // e^{+2*pi*i*tid/128}
        tw[tid] = make_float2(c, s);
    }
}

// ---------------------------------------------------------------------------
// Kernel 1a: row FFTs of x.  grid (BATCH, 4), block 128 (32 lines x 4 thr).
// ---------------------------------------------------------------------------
__global__ __launch_bounds__(128) void k_fft_rows(const float* __restrict__ x) {
    __shared__ float2 tw[64];
    const int tid = threadIdx.x;
    build_tw(tw, tid);
    __syncthreads();

    const int b    = blockIdx.x;
    const int line = blockIdx.y * 32 + (tid >> 2);
    const int t    = tid & 3;

    float2 v[32];
    const float* xb = x + b * MN + line * MDIM + 32 * t;
    #pragma unroll
    for (int j = 0; j < 32; ++j) v[j] = make_float2(xb[j], 0.f);

    dif_line4<-1>(v, t, tw);

    float2* dst = &g_T[b][line * MDIM + 32 * t];
    #pragma unroll
    for (int j = 0; j < 32; ++j) dst[j] = v[j];
}

// ---------------------------------------------------------------------------
// Kernel 1b: column FFTs.  grid (BATCH, 4), block 128. Natural-order output.
// ---------------------------------------------------------------------------
__global__ __launch_bounds__(128) void k_fft_cols() {
    __shared__ float2 tw[64];
    const int tid = threadIdx.x;
    build_tw(tw, tid);
    __syncthreads();

    const int b = blockIdx.x;
    const int q = blockIdx.y * 32 + (tid >> 2);   // pos-column
    const int t = tid & 3;

    float2 v[32];
    #pragma unroll
    for (int j = 0; j < 32; ++j) v[j] = g_T[b][(32 * t + j) * MDIM + q];

    dif_line4<-1>(v, t, tw);

    const int bq = (int)(__brev((unsigned)q) >> 25);
    #pragma unroll
    for (int j = 0; j < 32; ++j) {
        int br = (int)(__brev((unsigned)(32 * t + j)) >> 25);
        g_X[b][br * MDIM + bq] = v[j];
    }
}

// ---------------------------------------------------------------------------
// Kernel 2: per (b,i): H = Re(conj(X) * fft2(abs_eps(ifft2(F_i*X)))).
// grid = BATCH*NFI, block = 1024 (128 lines x 8 threads).
// ---------------------------------------------------------------------------
__global__ __launch_bounds__(1024, 1) void k_main(const float* __restrict__ F) {
    extern __shared__ float2 sm[];
    float2* tile = sm;
    float2* tw   = sm + MDIM * MDIM;
    const int tid  = threadIdx.x;
    const int line = tid >> 3, t = tid & 7;
    const int b = blockIdx.x >> 5;
    const int i = blockIdx.x & 31;

    build_tw(tw, tid);
    __syncthreads();

    const int base = line * MDIM + 16 * t;
    const float* __restrict__ Fi = F + i * MN + base;
    float2 v[16];
    #pragma unroll
    for (int j = 0; j < 16; ++j) {
        float  f  = Fi[j];
        float2 xv = g_X[b][base + j];
        v[j] = make_float2(f * xv.x, f * xv.y);
    }

    dif_line8<1>(v, t, tw);                          // inverse over cols
    #pragma unroll
    for (int j = 0; j < 16; ++j) tile[smaddr(line, 16 * t + j)] = v[j];
    __syncthreads();
    #pragma unroll
    for (int j = 0; j < 16; ++j) v[j] = tile[smaddr(16 * t + j, line)];
    dif_line8<1>(v, t, tw);                          // inverse over rows

    const float sc = 1.f / (float)MN;
    #pragma unroll
    for (int j = 0; j < 16; ++j) {
        float re = v[j].x * sc, im = v[j].y * sc;
        v[j] = make_float2(sqrtf(re * re + im * im + EPSV), 0.f);
    }

    dit_line8<-1>(v, t, tw);                         // forward over rows (regs)
    __syncthreads();
    #pragma unroll
    for (int j = 0; j < 16; ++j) tile[smaddr(16 * t + j, line)] = v[j];
    __syncthreads();
    #pragma unroll
    for (int j = 0; j < 16; ++j) v[j] = tile[smaddr(line, 16 * t + j)];
    dit_line8<-1>(v, t, tw);                         // forward over cols -> XA natural

    float* __restrict__ Hrow = g_H[b][i] + base;
    #pragma unroll
    for (int j = 0; j < 16; ++j) {
        float2 xv = g_X[b][base + j];
        Hrow[j] = v[j].x * xv.x + v[j].y * xv.y;     // Re(conj(X)*XA)
    }
}

// ---------------------------------------------------------------------------
// Kernel 3 (R13 form): out[b,p] = (1/MN^2)*sum_k H[b,i0(p),k]*F[i1(p),k]^2
// grid = (NPAIR, BATCH), block = 256. float4 streaming, no atomics.
// ---------------------------------------------------------------------------
__global__ __launch_bounds__(256) void k_reduce(const float* __restrict__ F,
                                               float* __restrict__ out) {
    const int p = blockIdx.x;
    const int b = blockIdx.y;

    int rem = p, i0 = 0, i1 = 0;
    bool done = false;
    #pragma unroll 1
    for (int j1 = 0; j1 < 4 && !done; ++j1) {
        const int n = (4 - j1) * 8 + 1;
        #pragma unroll 1
        for (int l1 = 0; l1 < 8 && !done; ++l1) {
            if (rem < n) {
                i0 = j1 * 8 + l1;
                if (rem == n - 1) i1 = 32;
                else              i1 = (j1 + rem / 8) * 8 + (rem % 8);
                done = true;
            } else rem -= n;
        }
    }

    const float4* __restrict__ h4 = (const float4*)g_H[b][i0];
    const float4* __restrict__ f4 = (const float4*)(F + i1 * MN);

    float s = 0.f;
    #pragma unroll 4
    for (int k = threadIdx.x; k < MN / 4; k += 256) {
        float4 hv = h4[k], fv = f4[k];
        s += hv.x * (fv.x * fv.x) + hv.y * (fv.y * fv.y)
           + hv.z * (fv.z * fv.z) + hv.w * (fv.w * fv.w);
    }

    __shared__ float wsum[8];
    #pragma unroll
    for (int o = 16; o; o >>= 1) s += __shfl_xor_sync(0xffffffffu, s, o);
    if ((threadIdx.x & 31) == 0) wsum[threadIdx.x >> 5] = s;
    __syncthreads();
    if (threadIdx.x < 32) {
        float vv = (threadIdx.x < 8) ? wsum[threadIdx.x] : 0.f;
        #pragma unroll
        for (int o = 4; o; o >>= 1) vv += __shfl_xor_sync(0xffffffffu, vv, o);
        if (threadIdx.x == 0)
            out[b * NPAIR + p] = vv * (1.f / ((float)MN * (float)MN));
    }
}

// ---------------------------------------------------------------------------
extern "C" void kernel_launch(void* const* d_in, const int* in_sizes, int n_in,
                              void* d_out, int out_size) {
    const float* x = (const float*)d_in[0];   // (B,1,128,128) float32
    const float* F = (const float*)d_in[1];   // (1,33,128,128) float32
    float* out = (float*)d_out;               // (B,672) float32

    const int SMEM = (MDIM * MDIM + 64) * (int)sizeof(float2);
    cudaFuncSetAttribute(k_main, cudaFuncAttributeMaxDynamicSharedMemorySize, SMEM);

    k_fft_rows<<<dim3(BATCH, 4), 128>>>(x);
    k_fft_cols<<<dim3(BATCH, 4), 128>>>();
    k_main<<<BATCH * NFI, 1024, SMEM>>>(F);
    k_reduce<<<dim3(NPAIR, BATCH), 256>>>(F, out);
}

// round 17
// speedup vs baseline: 1.4336x; 1.2109x over previous
#include <cuda_runtime.h>
#include <math.h>

// Scattering third-order via Parseval identity:
//   out[b,i,j] = (1/MN^2) * sum_k F_j[k]^2 * Re( conj(X[b,k]) * XA_i[b,k] )
// X = fft2(x), XA_i = fft2(abs_eps(ifft2(F_i * X))).
//
// 4-threads-per-line register FFT engine (32 float2/thread), shfl_xor for the
// two cross-thread stages. Inverse = DIF (natural->bitrev positions), forward
// = DIT (bitrev->natural): spatial domain stays bit-reversed, abs is
// pointwise, so no permutations needed mid-pipeline.
//
// The former monolithic k_main (64 CTAs, 132KB smem, half the chip idle) is
// split into 3 streaming kernels of 256 small CTAs each:
//   kA: row inverse FFT of F_i*X        (contiguous R/W)
//   kB: col inverse FFT -> abs -> col forward FFT (smem-transposed slab, regs)
//   kC: row forward FFT -> H            (contiguous R/W)

#define MDIM   128
#define MN     16384
#define NFI    32
#define NIMG   (BATCH*NFI)
#define NPAIR  672
#define BATCH  2
#define EPSV   1e-6f

__device__ float2 g_X[BATCH][MN];          // fft2(x), natural order
__device__ float2 g_T[BATCH][MN];          // row-FFT intermediate for x
__device__ float2 g_W[NIMG][MN];           // per-image working tile [R][pc]
__device__ float  g_H[BATCH][NFI][MN];     // Re(conj(X) * XA_i)

// ---------------------------------------------------------------------------
__device__ __forceinline__ float2 shflx(float2 a, int m) {
    a.x = __shfl_xor_sync(0xffffffffu, a.x, m);
    a.y = __shfl_xor_sync(0xffffffffu, a.y, m);
    return a;
}

template<int SGN>  // SGN = -1 forward (numpy fft), +1 inverse (unnormalized)
__device__ __forceinline__ float2 cmulw(float2 a, float2 w) {
    float wi = (float)SGN * w.y;
    return make_float2(a.x * w.x - a.y * wi, a.x * wi + a.y * w.x);
}

template<int SGN>
__device__ __forceinline__ void bfly_dif(float2& a, float2& b, float2 w) {
    float ur = a.x - b.x, ui = a.y - b.y;
    a.x += b.x; a.y += b.y;
    float wi = (float)SGN * w.y;
    b.x = ur * w.x - ui * wi;
    b.y = ur * wi + ui * w.x;
}

template<int SGN>
__device__ __forceinline__ void bfly_dit(float2& a, float2& b, float2 w) {
    float wi = (float)SGN * w.y;
    float tr = b.x * w.x - b.y * wi;
    float ti = b.x * wi + b.y * w.x;
    b.x = a.x - tr; b.y = a.y - ti;
    a.x += tr; a.y += ti;
}

// DIF, 4 threads/line, thread t owns positions 32t+j. natural in -> bitrev pos.
template<int SGN>
__device__ __forceinline__ void dif_line4(float2 v[32], int t, const float2* __restrict__ tw) {
    {   const float2* twm = tw + ((t & 1) << 5);
        const bool hi = (t >= 2);
        #pragma unroll
        for (int j = 0; j < 32; ++j) {
            float2 a = v[j], p = shflx(a, 2);
            v[j] = hi ? cmulw<SGN>(make_float2(p.x - a.x, p.y - a.y), twm[j])
                      : make_float2(a.x + p.x, a.y + p.y);
        }
    }
    {   const bool hi = (t & 1);
        #pragma unroll
        for (int j = 0; j < 32; ++j) {
            float2 a = v[j], p = shflx(a, 1);
            v[j] = hi ? cmulw<SGN>(make_float2(p.x - a.x, p.y - a.y), tw[2 * j])
                      : make_float2(a.x + p.x, a.y + p.y);
        }
    }
    #pragma unroll
    for (int j = 0; j < 16; ++j) bfly_dif<SGN>(v[j], v[j + 16], tw[4 * j]);
    #pragma unroll
    for (int b = 0; b < 32; b += 16)
        #pragma unroll
        for (int j = 0; j < 8; ++j) bfly_dif<SGN>(v[b + j], v[b + j + 8], tw[8 * j]);
    #pragma unroll
    for (int b = 0; b < 32; b += 8)
        #pragma unroll
        for (int j = 0; j < 4; ++j) bfly_dif<SGN>(v[b + j], v[b + j + 4], tw[16 * j]);
    #pragma unroll
    for (int b = 0; b < 32; b += 4)
        #pragma unroll
        for (int j = 0; j < 2; ++j) bfly_dif<SGN>(v[b + j], v[b + j + 2], tw[32 * j]);
    #pragma unroll
    for (int b = 0; b < 32; b += 2) {
        float2 u = v[b], w2 = v[b + 1];
        v[b]     = make_float2(u.x + w2.x, u.y + w2.y);
        v[b + 1] = make_float2(u.x - w2.x, u.y - w2.y);
    }
}

// DIT, 4 threads/line: bitrev positions in -> natural out.
template<int SGN>
__device__ __forceinline__ void dit_line4(float2 v[32], int t, const float2* __restrict__ tw) {
    #pragma unroll
    for (int b = 0; b < 32; b += 2) {
        float2 u = v[b], w2 = v[b + 1];
        v[b]     = make_float2(u.x + w2.x, u.y + w2.y);
        v[b + 1] = make_float2(u.x - w2.x, u.y - w2.y);
    }
    #pragma unroll
    for (int b = 0; b < 32; b += 4)
        #pragma unroll
        for (int j = 0; j < 2; ++j) bfly_dit<SGN>(v[b + j], v[b + j + 2], tw[32 * j]);
    #pragma unroll
    for (int b = 0; b < 32; b += 8)
        #pragma unroll
        for (int j = 0; j < 4; ++j) bfly_dit<SGN>(v[b + j], v[b + j + 4], tw[16 * j]);
    #pragma unroll
    for (int b = 0; b < 32; b += 16)
        #pragma unroll
        for (int j = 0; j < 8; ++j) bfly_dit<SGN>(v[b + j], v[b + j + 8], tw[8 * j]);
    #pragma unroll
    for (int j = 0; j < 16; ++j) bfly_dit<SGN>(v[j], v[j + 16], tw[4 * j]);
    {   const bool hi = (t & 1);
        #pragma unroll
        for (int j = 0; j < 32; ++j) {
            float2 a = v[j];
            if (hi) a = cmulw<SGN>(a, tw[2 * j]);
            float2 p = shflx(a, 1);
            v[j] = hi ? make_float2(p.x - a.x, p.y - a.y)
                      : make_float2(a.x + p.x, a.y + p.y);
        }
    }
    {   const float2* twm = tw + ((t & 1) << 5);
        const bool hi = (t >= 2);
        #pragma unroll
        for (int j = 0; j < 32; ++j) {
            float2 a = v[j];
            if (hi) a = cmulw<SGN>(a, twm[j]);
            float2 p = shflx(a, 2);
            v[j] = hi ? make_float2(p.x - a.x, p.y - a.y)
                      : make_float2(a.x + p.x, a.y + p.y);
        }
    }
}

__device__ __forceinline__ void build_tw(float2* tw, int tid) {
    if (tid < 64) {
        float s, c;
        sincospif((float)tid / 64.f, &s, &c);   // e^{+2*pi*i*tid/128}
        tw[tid] = make_float2(c, s);
    }
}

// ---------------------------------------------------------------------------
// x FFT, pass 1: row FFTs.  grid (BATCH, 4), block 128.
// ---------------------------------------------------------------------------
__global__ __launch_bounds__(128) void k_fft_rows(const float* __restrict__ x) {
    __shared__ float2 tw[64];
    const int tid = threadIdx.x;
    build_tw(tw, tid);
    __syncthreads();

    const int b    = blockIdx.x;
    const int line = blockIdx.y * 32 + (tid >> 2);
    const int t    = tid & 3;

    float2 v[32];
    const float* xb = x + b * MN + line * MDIM + 32 * t;
    #pragma unroll
    for (int j = 0; j < 32; ++j) v[j] = make_float2(xb[j], 0.f);

    dif_line4<-1>(v, t, tw);

    float2* dst = &g_T[b][line * MDIM + 32 * t];
    #pragma unroll
    for (int j = 0; j < 32; ++j) dst[j] = v[j];
}

// ---------------------------------------------------------------------------
// x FFT, pass 2: column FFTs, natural-order output. grid (BATCH, 4), block 128.
// ---------------------------------------------------------------------------
__global__ __launch_bounds__(128) void k_fft_cols() {
    __shared__ float2 tw[64];
    const int tid = threadIdx.x;
    build_tw(tw, tid);
    __syncthreads();

    const int b = blockIdx.x;
    const int q = blockIdx.y * 32 + (tid >> 2);   // bitrev col position
    const int t = tid & 3;

    float2 v[32];
    #pragma unroll
    for (int j = 0; j < 32; ++j) v[j] = g_T[b][(32 * t + j) * MDIM + q];

    dif_line4<-1>(v, t, tw);

    const int bq = (int)(__brev((unsigned)q) >> 25);
    #pragma unroll
    for (int j = 0; j < 32; ++j) {
        int br = (int)(__brev((unsigned)(32 * t + j)) >> 25);
        g_X[b][br * MDIM + bq] = v[j];
    }
}

// ---------------------------------------------------------------------------
// kA: W[img][R][pc] = InvRowFFT( F_i[R,:] * X[b][R,:] ).
// grid (NIMG, 4), block 128 (32 rows x 4 threads).
// ---------------------------------------------------------------------------
__global__ __launch_bounds__(128) void kA(const float* __restrict__ F) {
    __shared__ float2 tw[64];
    const int tid = threadIdx.x;
    build_tw(tw, tid);
    __syncthreads();

    const int img = blockIdx.x;
    const int b   = img >> 5, i = img & 31;
    const int R   = blockIdx.y * 32 + (tid >> 2);
    const int t   = tid & 3;
    const int base = R * MDIM + 32 * t;

    const float*  __restrict__ Fi = F + i * MN + base;
    const float2* __restrict__ Xr = &g_X[b][base];

    float2 v[32];
    #pragma unroll
    for (int j = 0; j < 32; ++j) {
        float f = Fi[j];
        float2 xv = Xr[j];
        v[j] = make_float2(f * xv.x, f * xv.y);
    }

    dif_line4<1>(v, t, tw);        // inverse over row axis -> bitrev pc

    float2* dst = &g_W[img][base];
    #pragma unroll
    for (int j = 0; j < 32; ++j) dst[j] = v[j];
}

// ---------------------------------------------------------------------------
// kB: per 32-column slab: inverse col FFT -> abs_eps -> forward col FFT.
// In-place on g_W. grid (NIMG, 4), block 128. Smem-transposed slab with an
// XOR swizzle so the 4-thread group reads (stride-32 rows) are conflict-free.
// ---------------------------------------------------------------------------
__global__ __launch_bounds__(128) void kB() {
    __shared__ float2 tw[64];
    __shared__ float2 slab[MDIM * 33];     // [r][c], stride 33, c XOR (r>>5)<<3
    const int tid = threadIdx.x;
    build_tw(tw, tid);
    __syncthreads();

    const int img = blockIdx.x;
    const int c0  = blockIdx.y * 32;       // slab's first pc column

    // coalesced load: rows x 32 cols
    #pragma unroll
    for (int idx = tid; idx < MDIM * 32; idx += 128) {
        int r = idx >> 5, c = idx & 31;
        slab[r * 33 + (c ^ ((r >> 5) << 3))] = g_W[img][r * MDIM + c0 + c];
    }
    __syncthreads();

    const int c = tid >> 2;                // column within slab
    const int t = tid & 3;

    float2 v[32];
    #pragma unroll
    for (int j = 0; j < 32; ++j) {
        int r = 32 * t + j;
        v[j] = slab[r * 33 + (c ^ (t << 3))];
    }

    dif_line4<1>(v, t, tw);                // inverse over col axis -> spatial

    const float sc = 1.f / (float)MN;      // full ifft2 normalization
    #pragma unroll
    for (int j = 0; j < 32; ++j) {
        float re = v[j].x * sc, im = v[j].y * sc;
        v[j] = make_float2(sqrtf(re * re + im * im + EPSV), 0.f);
    }

    dit_line4<-1>(v, t, tw);               // forward over col axis -> natural R

    #pragma unroll
    for (int j = 0; j < 32; ++j) {
        int r = 32 * t + j;
        slab[r * 33 + (c ^ (t << 3))] = v[j];
    }
    __syncthreads();

    #pragma unroll
    for (int idx = tid; idx < MDIM * 32; idx += 128) {
        int r = idx >> 5, cc = idx & 31;
        g_W[img][r * MDIM + c0 + cc] = slab[r * 33 + (cc ^ ((r >> 5) << 3))];
    }
}

// ---------------------------------------------------------------------------
// kC: forward row FFT (bitrev pc -> natural C), then H = Re(conj(X)*XA).
// grid (NIMG, 4), block 128.
// ---------------------------------------------------------------------------
__global__ __launch_bounds__(128) void kC() {
    __shared__ float2 tw[64];
    const int tid = threadIdx.x;
    build_tw(tw, tid);
    __syncthreads();

    const int img = blockIdx.x;
    const int b   = img >> 5, i = img & 31;
    const int R   = blockIdx.y * 32 + (tid >> 2);
    const int t   = tid & 3;
    const int base = R * MDIM + 32 * t;

    float2 v[32];
    const float2* src = &g_W[img][base];
    #pragma unroll
    for (int j = 0; j < 32; ++j) v[j] = src[j];

    dit_line4<-1>(v, t, tw);               // forward over row axis -> natural C

    const float2* __restrict__ Xr = &g_X[b][base];
    float* __restrict__ Hrow = g_H[b][i] + base;
    #pragma unroll
    for (int j = 0; j < 32; ++j) {
        float2 xv = Xr[j];
        Hrow[j] = v[j].x * xv.x + v[j].y * xv.y;   // Re(conj(X)*XA)
    }
}

// ---------------------------------------------------------------------------
// k_reduce: out[b,p] = (1/MN^2)*sum_k H[b,i0(p),k]*F[i1(p),k]^2
// grid = (NPAIR, BATCH), block = 256.
// ---------------------------------------------------------------------------
__global__ __launch_bounds__(256) void k_reduce(const float* __restrict__ F,
                                               float* __restrict__ out) {
    const int p = blockIdx.x;
    const int b = blockIdx.y;

    int rem = p, i0 = 0, i1 = 0;
    bool done = false;
    #pragma unroll 1
    for (int j1 = 0; j1 < 4 && !done; ++j1) {
        const int n = (4 - j1) * 8 + 1;
        #pragma unroll 1
        for (int l1 = 0; l1 < 8 && !done; ++l1) {
            if (rem < n) {
                i0 = j1 * 8 + l1;
                if (rem == n - 1) i1 = 32;
                else              i1 = (j1 + rem / 8) * 8 + (rem % 8);
                done = true;
            } else rem -= n;
        }
    }

    const float4* __restrict__ h4 = (const float4*)g_H[b][i0];
    const float4* __restrict__ f4 = (const float4*)(F + i1 * MN);

    float s = 0.f;
    #pragma unroll 4
    for (int k = threadIdx.x; k < MN / 4; k += 256) {
        float4 hv = h4[k], fv = f4[k];
        s += hv.x * (fv.x * fv.x) + hv.y * (fv.y * fv.y)
           + hv.z * (fv.z * fv.z) + hv.w * (fv.w * fv.w);
    }

    __shared__ float wsum[8];
    #pragma unroll
    for (int o = 16; o; o >>= 1) s += __shfl_xor_sync(0xffffffffu, s, o);
    if ((threadIdx.x & 31) == 0) wsum[threadIdx.x >> 5] = s;
    __syncthreads();
    if (threadIdx.x < 32) {
        float vv = (threadIdx.x < 8) ? wsum[threadIdx.x] : 0.f;
        #pragma unroll
        for (int o = 4; o; o >>= 1) vv += __shfl_xor_sync(0xffffffffu, vv, o);
        if (threadIdx.x == 0)
            out[b * NPAIR + p] = vv * (1.f / ((float)MN * (float)MN));
    }
}

// ---------------------------------------------------------------------------
extern "C" void kernel_launch(void* const* d_in, const int* in_sizes, int n_in,
                              void* d_out, int out_size) {
    const float* x = (const float*)d_in[0];   // (B,1,128,128) float32
    const float* F = (const float*)d_in[1];   // (1,33,128,128) float32
    float* out = (float*)d_out;               // (B,672) float32

    k_fft_rows<<<dim3(BATCH, 4), 128>>>(x);
    k_fft_cols<<<dim3(BATCH, 4), 128>>>();
    kA<<<dim3(NIMG, 4), 128>>>(F);
    kB<<<dim3(NIMG, 4), 128>>>();
    kC<<<dim3(NIMG, 4), 128>>>();
    k_reduce<<<dim3(NPAIR, BATCH), 256>>>(F, out);
}